// round 15
// baseline (speedup 1.0000x reference)
#include <cuda_runtime.h>
#include <cuda_fp16.h>
#include <cstdint>

#define TOKENS 4096
#define DIN    1024
#define DHID   4096
#define DOUT   1024
#define NEXP   8

// ---------------- device scratch ----------------
__device__ __half g_xh [TOKENS * DIN];                          // x fp16 [M][K]
__device__ __half g_B1 [(NEXP + 1) * (size_t)DIN * DHID];       // W1 [e][K][N] + Wg1 (e=8), fp16
__device__ __half g_W2h[(size_t)NEXP * DHID * DOUT];            // W2 [e][K][N] fp16
__device__ __half g_H  [(NEXP + 1) * (size_t)TOKENS * DHID];    // H[e][b][h]; slot 8 = gating hidden
__device__ float  g_b1a[(NEXP + 1) * DHID];                     // b1 (e<8) ++ bg1 (e=8)
__device__ float  g_gate[TOKENS * NEXP];

// ---------------- PTX helpers ----------------
__device__ __forceinline__ void cp_async16(unsigned dst, const void* src) {
    asm volatile("cp.async.cg.shared.global [%0], [%1], 16;\n" :: "r"(dst), "l"(src));
}
__device__ __forceinline__ void cp_commit() {
    asm volatile("cp.async.commit_group;\n" ::: "memory");
}
__device__ __forceinline__ void cp_wait1() {
    asm volatile("cp.async.wait_group 1;\n" ::: "memory");
}
__device__ __forceinline__ void ldsm_x4(uint32_t* r, unsigned addr) {
    asm volatile("ldmatrix.sync.aligned.m8n8.x4.shared.b16 {%0,%1,%2,%3}, [%4];\n"
                 : "=r"(r[0]), "=r"(r[1]), "=r"(r[2]), "=r"(r[3]) : "r"(addr));
}
__device__ __forceinline__ void ldsm_x4_t(uint32_t* r, unsigned addr) {
    asm volatile("ldmatrix.sync.aligned.m8n8.x4.trans.shared.b16 {%0,%1,%2,%3}, [%4];\n"
                 : "=r"(r[0]), "=r"(r[1]), "=r"(r[2]), "=r"(r[3]) : "r"(addr));
}
__device__ __forceinline__ void mma16816(float* c, const uint32_t* a, uint32_t b0, uint32_t b1) {
    asm volatile("mma.sync.aligned.m16n8k16.row.col.f32.f16.f16.f32 "
                 "{%0,%1,%2,%3},{%4,%5,%6,%7},{%8,%9},{%0,%1,%2,%3};\n"
                 : "+f"(c[0]), "+f"(c[1]), "+f"(c[2]), "+f"(c[3])
                 : "r"(a[0]), "r"(a[1]), "r"(a[2]), "r"(a[3]), "r"(b0), "r"(b1));
}

// ---------------- fp32 -> fp16 convert (32B/thread) ----------------
__global__ void cvt_f32_f16(const float4* __restrict__ src, __half2* __restrict__ dst, int n4) {
    int i = (blockIdx.x * blockDim.x + threadIdx.x) * 2;   // float4 units
    if (i >= n4) return;
    float4 a = src[i], b = src[i + 1];
    __half2 h[4];
    h[0] = __floats2half2_rn(a.x, a.y);
    h[1] = __floats2half2_rn(a.z, a.w);
    h[2] = __floats2half2_rn(b.x, b.y);
    h[3] = __floats2half2_rn(b.z, b.w);
    *(float4*)(dst + i * 2) = *(float4*)h;   // 16B store of 8 halves
}

// pack b1 (8x4096) ++ bg1 (4096) into one bias table
__global__ void pack_bias(const float* __restrict__ b1, const float* __restrict__ bg1,
                          float* __restrict__ dst) {
    int i = blockIdx.x * 256 + threadIdx.x;
    if (i < NEXP * DHID) dst[i] = b1[i];
    else if (i < (NEXP + 1) * DHID) dst[i] = bg1[i - NEXP * DHID];
}

// ---------------- fused gating softmax + out initialization ----------------
__global__ void __launch_bounds__(256) gate_out_kernel(
    const __half* __restrict__ Hg, const float* __restrict__ Wg2,
    const float* __restrict__ bg2, const float* __restrict__ b2,
    float* __restrict__ gate, float* __restrict__ out)
{
    const int warp = threadIdx.x >> 5, lane = threadIdx.x & 31;
    const int row0 = (blockIdx.x * 8 + warp) * 8;       // 8 rows per warp

    float a[8][8];
#pragma unroll
    for (int r = 0; r < 8; r++)
#pragma unroll
        for (int j = 0; j < NEXP; j++) a[r][j] = 0.f;

    for (int k2 = lane; k2 < DHID / 2; k2 += 32) {
        const float4* w = (const float4*)(Wg2 + (2 * k2) * NEXP);
        float4 w00 = w[0], w01 = w[1];
        float4 w10 = w[2], w11 = w[3];
#pragma unroll
        for (int r = 0; r < 8; r++) {
            float2 xv = __half22float2(
                *(const __half2*)(Hg + (long long)(row0 + r) * DHID + 2 * k2));
            a[r][0] += xv.x * w00.x + xv.y * w10.x;
            a[r][1] += xv.x * w00.y + xv.y * w10.y;
            a[r][2] += xv.x * w00.z + xv.y * w10.z;
            a[r][3] += xv.x * w00.w + xv.y * w10.w;
            a[r][4] += xv.x * w01.x + xv.y * w11.x;
            a[r][5] += xv.x * w01.y + xv.y * w11.y;
            a[r][6] += xv.x * w01.z + xv.y * w11.z;
            a[r][7] += xv.x * w01.w + xv.y * w11.w;
        }
    }
#pragma unroll
    for (int o = 16; o > 0; o >>= 1)
#pragma unroll
        for (int r = 0; r < 8; r++)
#pragma unroll
            for (int j = 0; j < NEXP; j++)
                a[r][j] += __shfl_xor_sync(0xffffffffu, a[r][j], o);

    float bg[NEXP];
#pragma unroll
    for (int j = 0; j < NEXP; j++) bg[j] = bg2[j];

#pragma unroll
    for (int r = 0; r < 8; r++) {
        float m = -1e30f;
#pragma unroll
        for (int j = 0; j < NEXP; j++) { a[r][j] += bg[j]; m = fmaxf(m, a[r][j]); }
        float s = 0.f;
#pragma unroll
        for (int j = 0; j < NEXP; j++) { a[r][j] = __expf(a[r][j] - m); s += a[r][j]; }
        const float inv = 1.f / s;
#pragma unroll
        for (int j = 0; j < NEXP; j++) a[r][j] *= inv;
    }

#pragma unroll
    for (int r = 0; r < 8; r++)
#pragma unroll
        for (int j = 0; j < NEXP; j++)
            if (lane == j) gate[(row0 + r) * NEXP + j] = a[r][j];

#pragma unroll
    for (int r = 0; r < 8; r++) {
        float* op = out + (long long)(row0 + r) * DOUT;
        for (int o = lane * 4; o < DOUT; o += 128) {
            float4 s = make_float4(0.f, 0.f, 0.f, 0.f);
#pragma unroll
            for (int j = 0; j < NEXP; j++) {
                float4 bb = *(const float4*)(b2 + j * DOUT + o);
                s.x += a[r][j] * bb.x;
                s.y += a[r][j] * bb.y;
                s.z += a[r][j] * bb.z;
                s.w += a[r][j] * bb.w;
            }
            *(float4*)(op + o) = s;
        }
    }
}

// ---------------- PERSISTENT fused fp16 GEMM ----------------
// Flat iteration space q = tile*KT + kt per CTA; 3-stage cp.async pipeline runs
// continuously ACROSS tile boundaries (no per-tile fill/drain bubble).
// A: [M][K] row-major fp16.  B: [K][N] row-major fp16.
// MODE 1: C = relu(A@B + bias_e)          -> fp16 (layer-1, 9 e-slabs incl. gating e=8)
// MODE 2: out += gate[b,e] * (A_e@B_e)    -> fp32 atomicAdd (layer-2, K=4096 per e)
constexpr int BM = 128, BN = 128, BK = 64, STAGES = 3;
constexpr int ASTR = BK + 8;          // 72 halves
constexpr int BSTR = BN + 8;          // 136 halves
constexpr int A_TILE = BM * ASTR;     // halves
constexpr int B_TILE = BK * BSTR;
constexpr int SMEM_BYTES = STAGES * (A_TILE + B_TILE) * 2;   // 107,520 B -> 1 CTA/SM

template <int MODE>
__global__ void __launch_bounds__(256) moe_gemm_p(
    const __half* __restrict__ Abase, long long aSlab, int lda,
    const __half* __restrict__ Bbase, long long bStride, int ldb,
    const float* __restrict__ biasBase, long long biasStride,
    const float* __restrict__ gate,
    void* __restrict__ Cbase, long long cStride, int ldc,
    int K, int ntiles, int tilesX, int tilesY)
{
    extern __shared__ __half sm_[];
    __half* As = sm_;
    __half* Bs = sm_ + STAGES * A_TILE;

    const int tid  = threadIdx.x;
    const int lane = tid & 31;
    const int warp = tid >> 5;
    const int wm = warp >> 1, wn = warp & 1;   // 4x2 warp grid, warp tile 32x64
    const int G   = gridDim.x;
    const int bid = blockIdx.x;

    const int KT = K / BK;
    const int nI = (ntiles - bid + G - 1) / G;     // tiles for this CTA
    if (nI <= 0) return;
    const int Q  = nI * KT;                        // flat iterations

    const unsigned sA0 = (unsigned)__cvta_generic_to_shared(As);
    const unsigned sB0 = (unsigned)__cvta_generic_to_shared(Bs);

    // issue loads for flat iteration q (tile/kt derived from q)
    auto load_q = [&](int q) {
        const int i  = q / KT;
        const int kt = q - i * KT;
        const int t  = bid + i * G;
        const int nx = t % tilesX;
        const int r2 = t / tilesX;
        const int my = r2 % tilesY;
        const int e  = r2 / tilesY;
        const int k0 = kt * BK;
        const __half* aSrc = Abase + (MODE == 2 ? (long long)e * aSlab : 0LL)
                           + (long long)(my * BM) * lda + k0;
        const __half* bSrc = Bbase + (long long)e * bStride
                           + (long long)k0 * ldb + nx * BN;
        const int buf = q % STAGES;
        const unsigned da = sA0 + buf * (A_TILE * 2);
        const unsigned db = sB0 + buf * (B_TILE * 2);
#pragma unroll
        for (int it = 0; it < 4; it++) {
            int c = tid + it * 256;
            int r = c >> 3, c8 = (c & 7) << 3;
            cp_async16(da + (unsigned)(r * ASTR + c8) * 2,
                       aSrc + (long long)r * lda + c8);
        }
#pragma unroll
        for (int it = 0; it < 4; it++) {
            int c = tid + it * 256;
            int r = c >> 4, c16 = (c & 15) << 3;
            cp_async16(db + (unsigned)(r * BSTR + c16) * 2,
                       bSrc + (long long)r * ldb + c16);
        }
        cp_commit();
    };

    float acc[2][8][4];
#pragma unroll
    for (int a = 0; a < 2; a++)
#pragma unroll
        for (int b = 0; b < 8; b++)
#pragma unroll
            for (int c = 0; c < 4; c++) acc[a][b][c] = 0.f;

    load_q(0);
    if (Q > 1) load_q(1);
    else       cp_commit();

    const int lr = lane & 15;
    const int lc = (lane >> 4) << 3;
    const int g  = lane >> 2;
    const int tg = lane & 3;

    for (int q = 0; q < Q; q++) {
        cp_wait1();
        __syncthreads();
        if (q + 2 < Q) load_q(q + 2);
        else           cp_commit();       // keep wait_group accounting aligned

        const int buf = q % STAGES;
        const unsigned aB = sA0 + buf * (A_TILE * 2);
        const unsigned bB = sB0 + buf * (B_TILE * 2);
#pragma unroll
        for (int ks = 0; ks < BK / 16; ks++) {
            uint32_t af[2][4];
#pragma unroll
            for (int mb = 0; mb < 2; mb++)
                ldsm_x4(af[mb], aB + (unsigned)((wm * 32 + mb * 16 + lr) * ASTR + ks * 16 + lc) * 2);
            uint32_t bf[4][4];
#pragma unroll
            for (int nb = 0; nb < 4; nb++)
                ldsm_x4_t(bf[nb], bB + (unsigned)((ks * 16 + lr) * BSTR + wn * 64 + nb * 16 + lc) * 2);
#pragma unroll
            for (int mb = 0; mb < 2; mb++)
#pragma unroll
                for (int nb = 0; nb < 4; nb++) {
                    mma16816(acc[mb][2 * nb],     af[mb], bf[nb][0], bf[nb][1]);
                    mma16816(acc[mb][2 * nb + 1], af[mb], bf[nb][2], bf[nb][3]);
                }
        }

        // ---- tile boundary: epilogue + acc reset (loads for next tile stay in flight) ----
        if ((q + 1) % KT == 0) {
            const int i  = q / KT;
            const int t  = bid + i * G;
            const int nx = t % tilesX;
            const int r2 = t / tilesX;
            const int my = r2 % tilesY;
            const int e  = r2 / tilesY;
            const int bm0 = my * BM, bn0 = nx * BN;

            if constexpr (MODE == 1) {
                __half* C = (__half*)Cbase + (long long)e * cStride;
                const float* bias = biasBase + (long long)e * biasStride;
#pragma unroll
                for (int mb = 0; mb < 2; mb++)
#pragma unroll
                    for (int ii = 0; ii < 2; ii++) {
                        const int row = bm0 + wm * 32 + mb * 16 + g + ii * 8;
#pragma unroll
                        for (int nb = 0; nb < 8; nb++) {
                            const int col = bn0 + wn * 64 + nb * 8 + tg * 2;
                            float v0 = fmaxf(acc[mb][nb][2 * ii + 0] + bias[col],     0.f);
                            float v1 = fmaxf(acc[mb][nb][2 * ii + 1] + bias[col + 1], 0.f);
                            *(__half2*)(C + (long long)row * ldc + col) = __floats2half2_rn(v0, v1);
                        }
                    }
            } else {
                float* C = (float*)Cbase;
#pragma unroll
                for (int mb = 0; mb < 2; mb++)
#pragma unroll
                    for (int ii = 0; ii < 2; ii++) {
                        const int row = bm0 + wm * 32 + mb * 16 + g + ii * 8;
                        const float gv = gate[row * NEXP + e];
#pragma unroll
                        for (int nb = 0; nb < 8; nb++) {
                            const int col = bn0 + wn * 64 + nb * 8 + tg * 2;
                            atomicAdd(C + (long long)row * ldc + col,     gv * acc[mb][nb][2 * ii + 0]);
                            atomicAdd(C + (long long)row * ldc + col + 1, gv * acc[mb][nb][2 * ii + 1]);
                        }
                    }
            }
#pragma unroll
            for (int a = 0; a < 2; a++)
#pragma unroll
                for (int b = 0; b < 8; b++)
#pragma unroll
                    for (int c = 0; c < 4; c++) acc[a][b][c] = 0.f;
        }
    }
}

// ---------------- launch ----------------
extern "C" void kernel_launch(void* const* d_in, const int* in_sizes, int n_in,
                              void* d_out, int out_size)
{
    const float* x   = (const float*)d_in[0];
    const float* W1  = (const float*)d_in[1];
    const float* b1  = (const float*)d_in[2];
    const float* W2  = (const float*)d_in[3];
    const float* b2  = (const float*)d_in[4];
    const float* Wg1 = (const float*)d_in[5];
    const float* bg1 = (const float*)d_in[6];
    const float* Wg2 = (const float*)d_in[7];
    const float* bg2 = (const float*)d_in[8];

    __half *xh, *B1, *W2h, *H;
    float *b1a, *gate;
    cudaGetSymbolAddress((void**)&xh,   g_xh);
    cudaGetSymbolAddress((void**)&B1,   g_B1);
    cudaGetSymbolAddress((void**)&W2h,  g_W2h);
    cudaGetSymbolAddress((void**)&H,    g_H);
    cudaGetSymbolAddress((void**)&b1a,  g_b1a);
    cudaGetSymbolAddress((void**)&gate, g_gate);

    int nsm = 0;
    cudaDeviceGetAttribute(&nsm, cudaDevAttrMultiProcessorCount, 0);
    if (nsm <= 0) nsm = 148;

    cudaFuncSetAttribute(moe_gemm_p<1>, cudaFuncAttributeMaxDynamicSharedMemorySize, SMEM_BYTES);
    cudaFuncSetAttribute(moe_gemm_p<2>, cudaFuncAttributeMaxDynamicSharedMemorySize, SMEM_BYTES);

    // fp32 -> fp16 converts (8 floats/thread) + bias pack
    cvt_f32_f16<<<TOKENS * DIN / 2048, 256>>>((const float4*)x, (__half2*)xh, TOKENS * DIN / 4);
    cvt_f32_f16<<<NEXP * DIN * DHID / 2048, 256>>>((const float4*)W1, (__half2*)B1, NEXP * DIN * DHID / 4);
    cvt_f32_f16<<<DIN * DHID / 2048, 256>>>((const float4*)Wg1,
        (__half2*)(B1 + (long long)NEXP * DIN * DHID), DIN * DHID / 4);
    cvt_f32_f16<<<NEXP * DHID * DOUT / 2048, 256>>>((const float4*)W2, (__half2*)W2h, NEXP * DHID * DOUT / 4);
    pack_bias<<<((NEXP + 1) * DHID + 255) / 256, 256>>>(b1, bg1, b1a);

    // 1) layer-1 persistent: H[e] = relu(x @ W1[e] + b1[e]); e=8 -> gating hidden
    //    tiles: 32 (N) x 32 (M) x 9 (E) = 9216
    moe_gemm_p<1><<<nsm, 256, SMEM_BYTES>>>(
        xh, 0, DIN,
        B1, (long long)DIN * DHID, DHID,
        b1a, DHID, nullptr,
        H, (long long)TOKENS * DHID, DHID,
        DIN, (NEXP + 1) * (TOKENS / BM) * (DHID / BN), DHID / BN, TOKENS / BM);

    // 2) fused gates + out init (from slot 8)
    gate_out_kernel<<<TOKENS / 64, 256>>>(
        H + (long long)NEXP * TOKENS * DHID, Wg2, bg2, b2, gate, (float*)d_out);

    // 3) layer-2 persistent, gate-scaled atomic accumulation into out
    //    tiles: 8 (N) x 32 (M) x 8 (E) = 2048
    moe_gemm_p<2><<<nsm, 256, SMEM_BYTES>>>(
        H, (long long)TOKENS * DHID, DHID,
        W2h, (long long)DHID * DOUT, DOUT,
        nullptr, 0, gate,
        d_out, 0, DOUT,
        DHID, NEXP * (TOKENS / BM) * (DOUT / BN), DOUT / BN, TOKENS / BM);
}

// round 16
// speedup vs baseline: 1.5145x; 1.5145x over previous
#include <cuda_runtime.h>
#include <cuda_fp16.h>
#include <cstdint>

#define TOKENS 4096
#define DIN    1024
#define DHID   4096
#define DOUT   1024
#define NEXP   8

// ---------------- device scratch ----------------
__device__ __half g_xh [TOKENS * DIN];                          // x fp16 [M][K]
__device__ __half g_B1 [(NEXP + 1) * (size_t)DIN * DHID];       // W1 [e][K][N] + Wg1 (e=8), fp16
__device__ __half g_W2h[(size_t)NEXP * DHID * DOUT];            // W2 [e][K][N] fp16
__device__ __half g_H  [(NEXP + 1) * (size_t)TOKENS * DHID];    // H[e][b][h]; slot 8 = gating hidden
__device__ float  g_b1a[(NEXP + 1) * DHID];                     // b1 (e<8) ++ bg1 (e=8)
__device__ float  g_gate[TOKENS * NEXP];

#define W2N (NEXP * DIN * DHID)     // 33,554,432 elements

// ---------------- PTX helpers ----------------
__device__ __forceinline__ void cp_async16(unsigned dst, const void* src) {
    asm volatile("cp.async.cg.shared.global [%0], [%1], 16;\n" :: "r"(dst), "l"(src));
}
__device__ __forceinline__ void cp_commit() {
    asm volatile("cp.async.commit_group;\n" ::: "memory");
}
__device__ __forceinline__ void cp_wait1() {
    asm volatile("cp.async.wait_group 1;\n" ::: "memory");
}
__device__ __forceinline__ void ldsm_x4(uint32_t* r, unsigned addr) {
    asm volatile("ldmatrix.sync.aligned.m8n8.x4.shared.b16 {%0,%1,%2,%3}, [%4];\n"
                 : "=r"(r[0]), "=r"(r[1]), "=r"(r[2]), "=r"(r[3]) : "r"(addr));
}
__device__ __forceinline__ void ldsm_x4_t(uint32_t* r, unsigned addr) {
    asm volatile("ldmatrix.sync.aligned.m8n8.x4.trans.shared.b16 {%0,%1,%2,%3}, [%4];\n"
                 : "=r"(r[0]), "=r"(r[1]), "=r"(r[2]), "=r"(r[3]) : "r"(addr));
}
__device__ __forceinline__ void mma16816(float* c, const uint32_t* a, uint32_t b0, uint32_t b1) {
    asm volatile("mma.sync.aligned.m16n8k16.row.col.f32.f16.f16.f32 "
                 "{%0,%1,%2,%3},{%4,%5,%6,%7},{%8,%9},{%0,%1,%2,%3};\n"
                 : "+f"(c[0]), "+f"(c[1]), "+f"(c[2]), "+f"(c[3])
                 : "r"(a[0]), "r"(a[1]), "r"(a[2]), "r"(a[3]), "r"(b0), "r"(b1));
}

// ---------------- fp32 -> fp16 convert (32B/thread) ----------------
__global__ void cvt_f32_f16(const float4* __restrict__ src, __half2* __restrict__ dst, int n4) {
    int i = (blockIdx.x * blockDim.x + threadIdx.x) * 2;   // float4 units
    if (i >= n4) return;
    float4 a = src[i], b = src[i + 1];
    __half2 h[4];
    h[0] = __floats2half2_rn(a.x, a.y);
    h[1] = __floats2half2_rn(a.z, a.w);
    h[2] = __floats2half2_rn(b.x, b.y);
    h[3] = __floats2half2_rn(b.z, b.w);
    *(float4*)(dst + i * 2) = *(float4*)h;   // 16B store of 8 halves
}

// pack b1 (8x4096) ++ bg1 (4096) into one bias table
__global__ void pack_bias(const float* __restrict__ b1, const float* __restrict__ bg1,
                          float* __restrict__ dst) {
    int i = blockIdx.x * 256 + threadIdx.x;
    if (i < NEXP * DHID) dst[i] = b1[i];
    else if (i < (NEXP + 1) * DHID) dst[i] = bg1[i - NEXP * DHID];
}

// ---------------- fused gating softmax + out initialization ----------------
__global__ void __launch_bounds__(256) gate_out_kernel(
    const __half* __restrict__ Hg, const float* __restrict__ Wg2,
    const float* __restrict__ bg2, const float* __restrict__ b2,
    float* __restrict__ gate, float* __restrict__ out)
{
    const int warp = threadIdx.x >> 5, lane = threadIdx.x & 31;
    const int row0 = (blockIdx.x * 8 + warp) * 8;       // 8 rows per warp

    float a[8][8];
#pragma unroll
    for (int r = 0; r < 8; r++)
#pragma unroll
        for (int j = 0; j < NEXP; j++) a[r][j] = 0.f;

    for (int k2 = lane; k2 < DHID / 2; k2 += 32) {
        const float4* w = (const float4*)(Wg2 + (2 * k2) * NEXP);
        float4 w00 = w[0], w01 = w[1];
        float4 w10 = w[2], w11 = w[3];
#pragma unroll
        for (int r = 0; r < 8; r++) {
            float2 xv = __half22float2(
                *(const __half2*)(Hg + (long long)(row0 + r) * DHID + 2 * k2));
            a[r][0] += xv.x * w00.x + xv.y * w10.x;
            a[r][1] += xv.x * w00.y + xv.y * w10.y;
            a[r][2] += xv.x * w00.z + xv.y * w10.z;
            a[r][3] += xv.x * w00.w + xv.y * w10.w;
            a[r][4] += xv.x * w01.x + xv.y * w11.x;
            a[r][5] += xv.x * w01.y + xv.y * w11.y;
            a[r][6] += xv.x * w01.z + xv.y * w11.z;
            a[r][7] += xv.x * w01.w + xv.y * w11.w;
        }
    }
#pragma unroll
    for (int o = 16; o > 0; o >>= 1)
#pragma unroll
        for (int r = 0; r < 8; r++)
#pragma unroll
            for (int j = 0; j < NEXP; j++)
                a[r][j] += __shfl_xor_sync(0xffffffffu, a[r][j], o);

    float bg[NEXP];
#pragma unroll
    for (int j = 0; j < NEXP; j++) bg[j] = bg2[j];

#pragma unroll
    for (int r = 0; r < 8; r++) {
        float m = -1e30f;
#pragma unroll
        for (int j = 0; j < NEXP; j++) { a[r][j] += bg[j]; m = fmaxf(m, a[r][j]); }
        float s = 0.f;
#pragma unroll
        for (int j = 0; j < NEXP; j++) { a[r][j] = __expf(a[r][j] - m); s += a[r][j]; }
        const float inv = 1.f / s;
#pragma unroll
        for (int j = 0; j < NEXP; j++) a[r][j] *= inv;
    }

#pragma unroll
    for (int r = 0; r < 8; r++)
#pragma unroll
        for (int j = 0; j < NEXP; j++)
            if (lane == j) gate[(row0 + r) * NEXP + j] = a[r][j];

#pragma unroll
    for (int r = 0; r < 8; r++) {
        float* op = out + (long long)(row0 + r) * DOUT;
        for (int o = lane * 4; o < DOUT; o += 128) {
            float4 s = make_float4(0.f, 0.f, 0.f, 0.f);
#pragma unroll
            for (int j = 0; j < NEXP; j++) {
                float4 bb = *(const float4*)(b2 + j * DOUT + o);
                s.x += a[r][j] * bb.x;
                s.y += a[r][j] * bb.y;
                s.z += a[r][j] * bb.z;
                s.w += a[r][j] * bb.w;
            }
            *(float4*)(op + o) = s;
        }
    }
}

// ---------------- fused fp16 GEMM (R8/R14 core, untouched inner loop) ----------------
// A: [M][K] row-major fp16.  B: [K][N] row-major fp16.
// MODE 1: C = relu(A@B + bias_e)          -> fp16 (layer-1, 9 z-slabs incl. gating e=8)
//         PLUS: prologue converts this CTA's slice of W2 fp32->fp16 (hidden under fill)
// MODE 2: out += gate[b,e] * (A_e@B_e)    -> fp32 atomicAdd (layer-2, z=e, K=4096)
constexpr int BM = 128, BN = 128, BK = 64, STAGES = 3;
constexpr int ASTR = BK + 8;          // 72 halves
constexpr int BSTR = BN + 8;          // 136 halves
constexpr int A_TILE = BM * ASTR;     // halves
constexpr int B_TILE = BK * BSTR;
constexpr int SMEM_BYTES = STAGES * (A_TILE + B_TILE) * 2;   // 107,520 B

template <int MODE>
__global__ void __launch_bounds__(256) moe_gemm(
    const __half* __restrict__ Abase, long long aSlab, int lda,
    const __half* __restrict__ Bbase, long long bStride, int ldb,
    const float* __restrict__ biasBase, long long biasStride,
    const float* __restrict__ gate,
    const float* __restrict__ w2src, __half* __restrict__ w2dst,
    void* __restrict__ Cbase, long long cStride, int ldc,
    int K)
{
    extern __shared__ __half sm_[];
    __half* As = sm_;
    __half* Bs = sm_ + STAGES * A_TILE;

    const int tid  = threadIdx.x;
    const int lane = tid & 31;
    const int warp = tid >> 5;
    const int wm = warp >> 1, wn = warp & 1;   // 4x2 warp grid, warp tile 32x64
    const int bm0 = blockIdx.y * BM;
    const int bn0 = blockIdx.x * BN;
    const int e   = blockIdx.z;

    const __half* Amat = Abase + (MODE == 2 ? (long long)e * aSlab : 0LL);
    const __half* Bmat = Bbase + (long long)e * bStride;

    const unsigned sA0 = (unsigned)__cvta_generic_to_shared(As);
    const unsigned sB0 = (unsigned)__cvta_generic_to_shared(Bs);

    float acc[2][8][4];
#pragma unroll
    for (int a = 0; a < 2; a++)
#pragma unroll
        for (int b = 0; b < 8; b++)
#pragma unroll
            for (int c = 0; c < 4; c++) acc[a][b][c] = 0.f;

    const int KT = K / BK;

    auto load_tile = [&](int kt, int buf) {
        const int k0 = kt * BK;
        const __half* aSrc = Amat + k0;
        const __half* bSrc = Bmat + (long long)k0 * ldb + bn0;
        const unsigned da = sA0 + buf * (A_TILE * 2);
        const unsigned db = sB0 + buf * (B_TILE * 2);
#pragma unroll
        for (int i = 0; i < 4; i++) {
            int c = tid + i * 256;
            int r = c >> 3, c8 = (c & 7) << 3;
            cp_async16(da + (unsigned)(r * ASTR + c8) * 2,
                       aSrc + (long long)(bm0 + r) * lda + c8);
        }
#pragma unroll
        for (int i = 0; i < 4; i++) {
            int c = tid + i * 256;
            int r = c >> 4, c16 = (c & 15) << 3;
            cp_async16(db + (unsigned)(r * BSTR + c16) * 2,
                       bSrc + (long long)r * ldb + c16);
        }
        cp_commit();
    };

    load_tile(0, 0);
    load_tile(1, 1);

    // ---- MODE1 prologue: convert this CTA's W2 slice while the pipeline fills ----
    if constexpr (MODE == 1) {
        const int gb = blockIdx.z * 1024 + blockIdx.y * 32 + blockIdx.x;   // grid 32x32x9
        const long long base = (long long)gb * 4096 + tid * 8;
#pragma unroll
        for (int p = 0; p < 2; p++) {
            const long long i = base + p * 2048;
            if (i < (long long)W2N) {
                float4 a4 = *(const float4*)(w2src + i);
                float4 b4 = *(const float4*)(w2src + i + 4);
                __half2 h[4];
                h[0] = __floats2half2_rn(a4.x, a4.y);
                h[1] = __floats2half2_rn(a4.z, a4.w);
                h[2] = __floats2half2_rn(b4.x, b4.y);
                h[3] = __floats2half2_rn(b4.z, b4.w);
                *(float4*)(w2dst + i) = *(float4*)h;
            }
        }
    }

    const int lr = lane & 15;
    const int lc = (lane >> 4) << 3;

    for (int kt = 0; kt < KT; kt++) {
        cp_wait1();
        __syncthreads();
        const int nt = kt + 2;
        if (nt < KT) load_tile(nt, nt % STAGES);
        else         cp_commit();     // empty group keeps wait accounting aligned

        const int buf = kt % STAGES;
        const unsigned aB = sA0 + buf * (A_TILE * 2);
        const unsigned bB = sB0 + buf * (B_TILE * 2);
#pragma unroll
        for (int ks = 0; ks < BK / 16; ks++) {
            uint32_t af[2][4];
#pragma unroll
            for (int mb = 0; mb < 2; mb++)
                ldsm_x4(af[mb], aB + (unsigned)((wm * 32 + mb * 16 + lr) * ASTR + ks * 16 + lc) * 2);
            uint32_t bf[4][4];
#pragma unroll
            for (int nb = 0; nb < 4; nb++)
                ldsm_x4_t(bf[nb], bB + (unsigned)((ks * 16 + lr) * BSTR + wn * 64 + nb * 16 + lc) * 2);
#pragma unroll
            for (int mb = 0; mb < 2; mb++)
#pragma unroll
                for (int nb = 0; nb < 4; nb++) {
                    mma16816(acc[mb][2 * nb],     af[mb], bf[nb][0], bf[nb][1]);
                    mma16816(acc[mb][2 * nb + 1], af[mb], bf[nb][2], bf[nb][3]);
                }
        }
    }

    // -------- epilogue --------
    const int g  = lane >> 2;
    const int tg = lane & 3;

    if constexpr (MODE == 1) {
        __half* C = (__half*)Cbase + (long long)e * cStride;
        const float* bias = biasBase + (long long)e * biasStride;
#pragma unroll
        for (int mb = 0; mb < 2; mb++)
#pragma unroll
            for (int i = 0; i < 2; i++) {
                const int row = bm0 + wm * 32 + mb * 16 + g + i * 8;
#pragma unroll
                for (int nb = 0; nb < 8; nb++) {
                    const int col = bn0 + wn * 64 + nb * 8 + tg * 2;
                    float v0 = fmaxf(acc[mb][nb][2 * i + 0] + bias[col],     0.f);
                    float v1 = fmaxf(acc[mb][nb][2 * i + 1] + bias[col + 1], 0.f);
                    *(__half2*)(C + (long long)row * ldc + col) = __floats2half2_rn(v0, v1);
                }
            }
    } else {
        float* C = (float*)Cbase;
#pragma unroll
        for (int mb = 0; mb < 2; mb++)
#pragma unroll
            for (int i = 0; i < 2; i++) {
                const int row = bm0 + wm * 32 + mb * 16 + g + i * 8;
                const float gv = gate[row * NEXP + e];
#pragma unroll
                for (int nb = 0; nb < 8; nb++) {
                    const int col = bn0 + wn * 64 + nb * 8 + tg * 2;
                    atomicAdd(C + (long long)row * ldc + col,     gv * acc[mb][nb][2 * i + 0]);
                    atomicAdd(C + (long long)row * ldc + col + 1, gv * acc[mb][nb][2 * i + 1]);
                }
            }
    }
}

// ---------------- launch ----------------
extern "C" void kernel_launch(void* const* d_in, const int* in_sizes, int n_in,
                              void* d_out, int out_size)
{
    const float* x   = (const float*)d_in[0];
    const float* W1  = (const float*)d_in[1];
    const float* b1  = (const float*)d_in[2];
    const float* W2  = (const float*)d_in[3];
    const float* b2  = (const float*)d_in[4];
    const float* Wg1 = (const float*)d_in[5];
    const float* bg1 = (const float*)d_in[6];
    const float* Wg2 = (const float*)d_in[7];
    const float* bg2 = (const float*)d_in[8];

    __half *xh, *B1, *W2h, *H;
    float *b1a, *gate;
    cudaGetSymbolAddress((void**)&xh,   g_xh);
    cudaGetSymbolAddress((void**)&B1,   g_B1);
    cudaGetSymbolAddress((void**)&W2h,  g_W2h);
    cudaGetSymbolAddress((void**)&H,    g_H);
    cudaGetSymbolAddress((void**)&b1a,  g_b1a);
    cudaGetSymbolAddress((void**)&gate, g_gate);

    cudaFuncSetAttribute(moe_gemm<1>, cudaFuncAttributeMaxDynamicSharedMemorySize, SMEM_BYTES);
    cudaFuncSetAttribute(moe_gemm<2>, cudaFuncAttributeMaxDynamicSharedMemorySize, SMEM_BYTES);

    // fp32 -> fp16 converts (8 floats/thread) + bias pack  (W2 convert folded into GEMM1)
    cvt_f32_f16<<<TOKENS * DIN / 2048, 256>>>((const float4*)x, (__half2*)xh, TOKENS * DIN / 4);
    cvt_f32_f16<<<NEXP * DIN * DHID / 2048, 256>>>((const float4*)W1, (__half2*)B1, NEXP * DIN * DHID / 4);
    cvt_f32_f16<<<DIN * DHID / 2048, 256>>>((const float4*)Wg1,
        (__half2*)(B1 + (long long)NEXP * DIN * DHID), DIN * DHID / 4);
    pack_bias<<<((NEXP + 1) * DHID + 255) / 256, 256>>>(b1, bg1, b1a);

    // 1) layer-1, 9 slabs + embedded W2 convert: H[e] = relu(x @ W1[e] + b1[e]); e=8 -> gating
    moe_gemm<1><<<dim3(DHID / BN, TOKENS / BM, NEXP + 1), 256, SMEM_BYTES>>>(
        xh, 0, DIN,
        B1, (long long)DIN * DHID, DHID,
        b1a, DHID, nullptr,
        W2, W2h,
        H, (long long)TOKENS * DHID, DHID, DIN);

    // 2) fused gates + out init (from slot 8)
    gate_out_kernel<<<TOKENS / 64, 256>>>(
        H + (long long)NEXP * TOKENS * DHID, Wg2, bg2, b2, gate, (float*)d_out);

    // 3) layer-2 split over experts, gate-scaled atomic accumulation into out
    moe_gemm<2><<<dim3(DOUT / BN, TOKENS / BM, NEXP), 256, SMEM_BYTES>>>(
        H, (long long)TOKENS * DHID, DHID,
        W2h, (long long)DHID * DOUT, DOUT,
        nullptr, 0, gate,
        nullptr, nullptr,
        d_out, 0, DOUT, DHID);
}

// round 17
// speedup vs baseline: 1.5235x; 1.0059x over previous
#include <cuda_runtime.h>
#include <cuda_fp16.h>
#include <cstdint>

#define TOKENS 4096
#define DIN    1024
#define DHID   4096
#define DOUT   1024
#define NEXP   8

// ---------------- device scratch ----------------
__device__ __half g_xh [TOKENS * DIN];                          // x fp16 [M][K]
__device__ __half g_B1 [(NEXP + 1) * (size_t)DIN * DHID];       // W1 [e][K][N] + Wg1 (e=8), fp16
__device__ __half g_W2h[(size_t)NEXP * DHID * DOUT];            // W2 [e][K][N] fp16
__device__ __half g_H  [(NEXP + 1) * (size_t)TOKENS * DHID];    // H[e][b][h]; slot 8 = gating hidden
__device__ float  g_b1a[(NEXP + 1) * DHID];                     // b1 (e<8) ++ bg1 (e=8)
__device__ float  g_gate[TOKENS * NEXP];

#define W2N (NEXP * DIN * DHID)     // 33,554,432 elements

// ---------------- PTX helpers ----------------
__device__ __forceinline__ void cp_async16(unsigned dst, const void* src) {
    asm volatile("cp.async.cg.shared.global [%0], [%1], 16;\n" :: "r"(dst), "l"(src));
}
__device__ __forceinline__ void cp_commit() {
    asm volatile("cp.async.commit_group;\n" ::: "memory");
}
__device__ __forceinline__ void cp_wait1() {
    asm volatile("cp.async.wait_group 1;\n" ::: "memory");
}
__device__ __forceinline__ void ldsm_x4(uint32_t* r, unsigned addr) {
    asm volatile("ldmatrix.sync.aligned.m8n8.x4.shared.b16 {%0,%1,%2,%3}, [%4];\n"
                 : "=r"(r[0]), "=r"(r[1]), "=r"(r[2]), "=r"(r[3]) : "r"(addr));
}
__device__ __forceinline__ void ldsm_x4_t(uint32_t* r, unsigned addr) {
    asm volatile("ldmatrix.sync.aligned.m8n8.x4.trans.shared.b16 {%0,%1,%2,%3}, [%4];\n"
                 : "=r"(r[0]), "=r"(r[1]), "=r"(r[2]), "=r"(r[3]) : "r"(addr));
}
__device__ __forceinline__ void mma16816(float* c, const uint32_t* a, uint32_t b0, uint32_t b1) {
    asm volatile("mma.sync.aligned.m16n8k16.row.col.f32.f16.f16.f32 "
                 "{%0,%1,%2,%3},{%4,%5,%6,%7},{%8,%9},{%0,%1,%2,%3};\n"
                 : "+f"(c[0]), "+f"(c[1]), "+f"(c[2]), "+f"(c[3])
                 : "r"(a[0]), "r"(a[1]), "r"(a[2]), "r"(a[3]), "r"(b0), "r"(b1));
}

// ---------------- unified prep: x/W1/Wg1 fp32->fp16 + bias pack, ONE launch ----------------
// CTA ranges (256 thr, 8 floats/thr = 2048 elems/CTA):
//   [0, 2048)        : x    (4M elems)   -> g_xh
//   [2048, 18432)    : W1   (32M elems)  -> g_B1
//   [18432, 20480)   : Wg1  (4M elems)   -> g_B1 + 8*DIN*DHID
//   [20480, 20624)   : bias pack (36864 floats, 1/thr)
#define PREP_X_CTAS   2048
#define PREP_W1_CTAS  16384
#define PREP_WG1_CTAS 2048
#define PREP_CVT_CTAS (PREP_X_CTAS + PREP_W1_CTAS + PREP_WG1_CTAS)   // 20480
#define PREP_BIAS_CTAS 144
#define PREP_CTAS (PREP_CVT_CTAS + PREP_BIAS_CTAS)                   // 20624

__global__ void __launch_bounds__(256) prep_kernel(
    const float* __restrict__ x,   const float* __restrict__ W1,
    const float* __restrict__ Wg1, const float* __restrict__ b1,
    const float* __restrict__ bg1,
    __half* __restrict__ xh, __half* __restrict__ B1, float* __restrict__ b1a)
{
    const int cta = blockIdx.x;
    if (cta < PREP_CVT_CTAS) {
        const float* src;
        __half* dst;
        long long off;
        if (cta < PREP_X_CTAS)            { src = x;   dst = xh; off = (long long)cta * 2048; }
        else if (cta < PREP_X_CTAS + PREP_W1_CTAS) {
            src = W1;  dst = B1;
            off = (long long)(cta - PREP_X_CTAS) * 2048;
        } else {
            src = Wg1; dst = B1 + (long long)NEXP * DIN * DHID;
            off = (long long)(cta - PREP_X_CTAS - PREP_W1_CTAS) * 2048;
        }
        const long long i = off + threadIdx.x * 8;
        float4 a4 = *(const float4*)(src + i);
        float4 b4 = *(const float4*)(src + i + 4);
        __half2 h[4];
        h[0] = __floats2half2_rn(a4.x, a4.y);
        h[1] = __floats2half2_rn(a4.z, a4.w);
        h[2] = __floats2half2_rn(b4.x, b4.y);
        h[3] = __floats2half2_rn(b4.z, b4.w);
        *(float4*)(dst + i) = *(float4*)h;
    } else {
        const int i = (cta - PREP_CVT_CTAS) * 256 + threadIdx.x;
        if (i < NEXP * DHID) b1a[i] = b1[i];
        else if (i < (NEXP + 1) * DHID) b1a[i] = bg1[i - NEXP * DHID];
    }
}

// ---------------- fused gating softmax + out initialization ----------------
__global__ void __launch_bounds__(256) gate_out_kernel(
    const __half* __restrict__ Hg, const float* __restrict__ Wg2,
    const float* __restrict__ bg2, const float* __restrict__ b2,
    float* __restrict__ gate, float* __restrict__ out)
{
    const int warp = threadIdx.x >> 5, lane = threadIdx.x & 31;
    const int row0 = (blockIdx.x * 8 + warp) * 8;       // 8 rows per warp

    float a[8][8];
#pragma unroll
    for (int r = 0; r < 8; r++)
#pragma unroll
        for (int j = 0; j < NEXP; j++) a[r][j] = 0.f;

    for (int k2 = lane; k2 < DHID / 2; k2 += 32) {
        const float4* w = (const float4*)(Wg2 + (2 * k2) * NEXP);
        float4 w00 = w[0], w01 = w[1];
        float4 w10 = w[2], w11 = w[3];
#pragma unroll
        for (int r = 0; r < 8; r++) {
            float2 xv = __half22float2(
                *(const __half2*)(Hg + (long long)(row0 + r) * DHID + 2 * k2));
            a[r][0] += xv.x * w00.x + xv.y * w10.x;
            a[r][1] += xv.x * w00.y + xv.y * w10.y;
            a[r][2] += xv.x * w00.z + xv.y * w10.z;
            a[r][3] += xv.x * w00.w + xv.y * w10.w;
            a[r][4] += xv.x * w01.x + xv.y * w11.x;
            a[r][5] += xv.x * w01.y + xv.y * w11.y;
            a[r][6] += xv.x * w01.z + xv.y * w11.z;
            a[r][7] += xv.x * w01.w + xv.y * w11.w;
        }
    }
#pragma unroll
    for (int o = 16; o > 0; o >>= 1)
#pragma unroll
        for (int r = 0; r < 8; r++)
#pragma unroll
            for (int j = 0; j < NEXP; j++)
                a[r][j] += __shfl_xor_sync(0xffffffffu, a[r][j], o);

    float bg[NEXP];
#pragma unroll
    for (int j = 0; j < NEXP; j++) bg[j] = bg2[j];

#pragma unroll
    for (int r = 0; r < 8; r++) {
        float m = -1e30f;
#pragma unroll
        for (int j = 0; j < NEXP; j++) { a[r][j] += bg[j]; m = fmaxf(m, a[r][j]); }
        float s = 0.f;
#pragma unroll
        for (int j = 0; j < NEXP; j++) { a[r][j] = __expf(a[r][j] - m); s += a[r][j]; }
        const float inv = 1.f / s;
#pragma unroll
        for (int j = 0; j < NEXP; j++) a[r][j] *= inv;
    }

#pragma unroll
    for (int r = 0; r < 8; r++)
#pragma unroll
        for (int j = 0; j < NEXP; j++)
            if (lane == j) gate[(row0 + r) * NEXP + j] = a[r][j];

#pragma unroll
    for (int r = 0; r < 8; r++) {
        float* op = out + (long long)(row0 + r) * DOUT;
        for (int o = lane * 4; o < DOUT; o += 128) {
            float4 s = make_float4(0.f, 0.f, 0.f, 0.f);
#pragma unroll
            for (int j = 0; j < NEXP; j++) {
                float4 bb = *(const float4*)(b2 + j * DOUT + o);
                s.x += a[r][j] * bb.x;
                s.y += a[r][j] * bb.y;
                s.z += a[r][j] * bb.z;
                s.w += a[r][j] * bb.w;
            }
            *(float4*)(op + o) = s;
        }
    }
}

// ---------------- fused fp16 GEMM (R8/R14 core, untouched inner loop) ----------------
// A: [M][K] row-major fp16.  B: [K][N] row-major fp16.
// MODE 1: C = relu(A@B + bias_e)          -> fp16 (layer-1, 9 z-slabs incl. gating e=8)
//         PLUS: prologue converts this CTA's slice of W2 fp32->fp16 (hidden under fill)
// MODE 2: out += gate[b,e] * (A_e@B_e)    -> fp32 atomicAdd (layer-2, z=e, K=4096)
constexpr int BM = 128, BN = 128, BK = 64, STAGES = 3;
constexpr int ASTR = BK + 8;          // 72 halves
constexpr int BSTR = BN + 8;          // 136 halves
constexpr int A_TILE = BM * ASTR;     // halves
constexpr int B_TILE = BK * BSTR;
constexpr int SMEM_BYTES = STAGES * (A_TILE + B_TILE) * 2;   // 107,520 B

template <int MODE>
__global__ void __launch_bounds__(256) moe_gemm(
    const __half* __restrict__ Abase, long long aSlab, int lda,
    const __half* __restrict__ Bbase, long long bStride, int ldb,
    const float* __restrict__ biasBase, long long biasStride,
    const float* __restrict__ gate,
    const float* __restrict__ w2src, __half* __restrict__ w2dst,
    void* __restrict__ Cbase, long long cStride, int ldc,
    int K)
{
    extern __shared__ __half sm_[];
    __half* As = sm_;
    __half* Bs = sm_ + STAGES * A_TILE;

    const int tid  = threadIdx.x;
    const int lane = tid & 31;
    const int warp = tid >> 5;
    const int wm = warp >> 1, wn = warp & 1;   // 4x2 warp grid, warp tile 32x64
    const int bm0 = blockIdx.y * BM;
    const int bn0 = blockIdx.x * BN;
    const int e   = blockIdx.z;

    const __half* Amat = Abase + (MODE == 2 ? (long long)e * aSlab : 0LL);
    const __half* Bmat = Bbase + (long long)e * bStride;

    const unsigned sA0 = (unsigned)__cvta_generic_to_shared(As);
    const unsigned sB0 = (unsigned)__cvta_generic_to_shared(Bs);

    float acc[2][8][4];
#pragma unroll
    for (int a = 0; a < 2; a++)
#pragma unroll
        for (int b = 0; b < 8; b++)
#pragma unroll
            for (int c = 0; c < 4; c++) acc[a][b][c] = 0.f;

    const int KT = K / BK;

    auto load_tile = [&](int kt, int buf) {
        const int k0 = kt * BK;
        const __half* aSrc = Amat + k0;
        const __half* bSrc = Bmat + (long long)k0 * ldb + bn0;
        const unsigned da = sA0 + buf * (A_TILE * 2);
        const unsigned db = sB0 + buf * (B_TILE * 2);
#pragma unroll
        for (int i = 0; i < 4; i++) {
            int c = tid + i * 256;
            int r = c >> 3, c8 = (c & 7) << 3;
            cp_async16(da + (unsigned)(r * ASTR + c8) * 2,
                       aSrc + (long long)(bm0 + r) * lda + c8);
        }
#pragma unroll
        for (int i = 0; i < 4; i++) {
            int c = tid + i * 256;
            int r = c >> 4, c16 = (c & 15) << 3;
            cp_async16(db + (unsigned)(r * BSTR + c16) * 2,
                       bSrc + (long long)r * ldb + c16);
        }
        cp_commit();
    };

    load_tile(0, 0);
    load_tile(1, 1);

    // ---- MODE1 prologue: convert this CTA's W2 slice while the pipeline fills ----
    if constexpr (MODE == 1) {
        const int gb = blockIdx.z * 1024 + blockIdx.y * 32 + blockIdx.x;   // grid 32x32x9
        const long long base = (long long)gb * 4096 + tid * 8;
#pragma unroll
        for (int p = 0; p < 2; p++) {
            const long long i = base + p * 2048;
            if (i < (long long)W2N) {
                float4 a4 = *(const float4*)(w2src + i);
                float4 b4 = *(const float4*)(w2src + i + 4);
                __half2 h[4];
                h[0] = __floats2half2_rn(a4.x, a4.y);
                h[1] = __floats2half2_rn(a4.z, a4.w);
                h[2] = __floats2half2_rn(b4.x, b4.y);
                h[3] = __floats2half2_rn(b4.z, b4.w);
                *(float4*)(w2dst + i) = *(float4*)h;
            }
        }
    }

    const int lr = lane & 15;
    const int lc = (lane >> 4) << 3;

    for (int kt = 0; kt < KT; kt++) {
        cp_wait1();
        __syncthreads();
        const int nt = kt + 2;
        if (nt < KT) load_tile(nt, nt % STAGES);
        else         cp_commit();     // empty group keeps wait accounting aligned

        const int buf = kt % STAGES;
        const unsigned aB = sA0 + buf * (A_TILE * 2);
        const unsigned bB = sB0 + buf * (B_TILE * 2);
#pragma unroll
        for (int ks = 0; ks < BK / 16; ks++) {
            uint32_t af[2][4];
#pragma unroll
            for (int mb = 0; mb < 2; mb++)
                ldsm_x4(af[mb], aB + (unsigned)((wm * 32 + mb * 16 + lr) * ASTR + ks * 16 + lc) * 2);
            uint32_t bf[4][4];
#pragma unroll
            for (int nb = 0; nb < 4; nb++)
                ldsm_x4_t(bf[nb], bB + (unsigned)((ks * 16 + lr) * BSTR + wn * 64 + nb * 16 + lc) * 2);
#pragma unroll
            for (int mb = 0; mb < 2; mb++)
#pragma unroll
                for (int nb = 0; nb < 4; nb++) {
                    mma16816(acc[mb][2 * nb],     af[mb], bf[nb][0], bf[nb][1]);
                    mma16816(acc[mb][2 * nb + 1], af[mb], bf[nb][2], bf[nb][3]);
                }
        }
    }

    // -------- epilogue --------
    const int g  = lane >> 2;
    const int tg = lane & 3;

    if constexpr (MODE == 1) {
        __half* C = (__half*)Cbase + (long long)e * cStride;
        const float* bias = biasBase + (long long)e * biasStride;
#pragma unroll
        for (int mb = 0; mb < 2; mb++)
#pragma unroll
            for (int i = 0; i < 2; i++) {
                const int row = bm0 + wm * 32 + mb * 16 + g + i * 8;
#pragma unroll
                for (int nb = 0; nb < 8; nb++) {
                    const int col = bn0 + wn * 64 + nb * 8 + tg * 2;
                    float v0 = fmaxf(acc[mb][nb][2 * i + 0] + bias[col],     0.f);
                    float v1 = fmaxf(acc[mb][nb][2 * i + 1] + bias[col + 1], 0.f);
                    *(__half2*)(C + (long long)row * ldc + col) = __floats2half2_rn(v0, v1);
                }
            }
    } else {
        float* C = (float*)Cbase;
#pragma unroll
        for (int mb = 0; mb < 2; mb++)
#pragma unroll
            for (int i = 0; i < 2; i++) {
                const int row = bm0 + wm * 32 + mb * 16 + g + i * 8;
                const float gv = gate[row * NEXP + e];
#pragma unroll
                for (int nb = 0; nb < 8; nb++) {
                    const int col = bn0 + wn * 64 + nb * 8 + tg * 2;
                    atomicAdd(C + (long long)row * ldc + col,     gv * acc[mb][nb][2 * i + 0]);
                    atomicAdd(C + (long long)row * ldc + col + 1, gv * acc[mb][nb][2 * i + 1]);
                }
            }
    }
}

// ---------------- launch ----------------
extern "C" void kernel_launch(void* const* d_in, const int* in_sizes, int n_in,
                              void* d_out, int out_size)
{
    const float* x   = (const float*)d_in[0];
    const float* W1  = (const float*)d_in[1];
    const float* b1  = (const float*)d_in[2];
    const float* W2  = (const float*)d_in[3];
    const float* b2  = (const float*)d_in[4];
    const float* Wg1 = (const float*)d_in[5];
    const float* bg1 = (const float*)d_in[6];
    const float* Wg2 = (const float*)d_in[7];
    const float* bg2 = (const float*)d_in[8];

    __half *xh, *B1, *W2h, *H;
    float *b1a, *gate;
    cudaGetSymbolAddress((void**)&xh,   g_xh);
    cudaGetSymbolAddress((void**)&B1,   g_B1);
    cudaGetSymbolAddress((void**)&W2h,  g_W2h);
    cudaGetSymbolAddress((void**)&H,    g_H);
    cudaGetSymbolAddress((void**)&b1a,  g_b1a);
    cudaGetSymbolAddress((void**)&gate, g_gate);

    cudaFuncSetAttribute(moe_gemm<1>, cudaFuncAttributeMaxDynamicSharedMemorySize, SMEM_BYTES);
    cudaFuncSetAttribute(moe_gemm<2>, cudaFuncAttributeMaxDynamicSharedMemorySize, SMEM_BYTES);

    // 0) unified prep: x/W1/Wg1 converts + bias pack (W2 convert folded into GEMM1)
    prep_kernel<<<PREP_CTAS, 256>>>(x, W1, Wg1, b1, bg1, xh, B1, b1a);

    // 1) layer-1, 9 slabs + embedded W2 convert: H[e] = relu(x @ W1[e] + b1[e]); e=8 -> gating
    moe_gemm<1><<<dim3(DHID / BN, TOKENS / BM, NEXP + 1), 256, SMEM_BYTES>>>(
        xh, 0, DIN,
        B1, (long long)DIN * DHID, DHID,
        b1a, DHID, nullptr,
        W2, W2h,
        H, (long long)TOKENS * DHID, DHID, DIN);

    // 2) fused gates + out init (from slot 8)
    gate_out_kernel<<<TOKENS / 64, 256>>>(
        H + (long long)NEXP * TOKENS * DHID, Wg2, bg2, b2, gate, (float*)d_out);

    // 3) layer-2 split over experts, gate-scaled atomic accumulation into out
    moe_gemm<2><<<dim3(DOUT / BN, TOKENS / BM, NEXP), 256, SMEM_BYTES>>>(
        H, (long long)TOKENS * DHID, DHID,
        W2h, (long long)DHID * DOUT, DOUT,
        nullptr, 0, gate,
        nullptr, nullptr,
        d_out, 0, DOUT, DHID);
}